// round 3
// baseline (speedup 1.0000x reference)
#include <cuda_runtime.h>
#include <cuda_bf16.h>
#include <cstdint>

// LightGCN propagation: acc = (x + P x + P^2 x + P^3 x) / 4, P = COO SpMM.
// Strategy: scatter-based SpMM with red.global.add.v4.f32 (16B vector atomics).
// h (12.8 MB) is L2-resident, so gathers and atomic RMWs are L2-bound; edge
// list streams from DRAM (~19 MB/layer).

static constexpr int N_NODES = 100000;
static constexpr int D       = 32;
static constexpr int ND      = N_NODES * D;          // 3,200,000 floats
static constexpr int ND4     = ND / 4;               // float4 count

// Scratch (no allocations allowed): two ping-pong layer buffers.
__device__ float g_buf0[ND];
__device__ float g_buf1[ND];

// ---------------------------------------------------------------------------
// init: out = x ; buf0 = 0 ; buf1 = 0      (float4-vectorized)
// ---------------------------------------------------------------------------
__global__ void k_init(const float4* __restrict__ x, float4* __restrict__ out) {
    int i = blockIdx.x * blockDim.x + threadIdx.x;
    if (i >= ND4) return;
    out[i] = x[i];
    float4 z = make_float4(0.f, 0.f, 0.f, 0.f);
    reinterpret_cast<float4*>(g_buf0)[i] = z;
    reinterpret_cast<float4*>(g_buf1)[i] = z;
}

// ---------------------------------------------------------------------------
// SpMM scatter: y[row[e]] += val[e] * h[col[e]]
// 8 threads per edge, one float4 (16B) each -> full 128B row per edge.
// Gather is coalesced (8 consecutive 16B chunks of the same row per 8 lanes).
// Scatter uses sm_90+ vector reduction red.global.add.v4.f32.
// ---------------------------------------------------------------------------
__global__ void k_spmm(const int* __restrict__ row,
                       const int* __restrict__ col,
                       const float* __restrict__ val,
                       const float* __restrict__ h,
                       float* __restrict__ y,
                       int nE) {
    int t = blockIdx.x * blockDim.x + threadIdx.x;
    if (t >= nE * 8) return;
    int e = t >> 3;
    int j = t & 7;

    int   c = __ldg(col + e);
    int   r = __ldg(row + e);
    float v = __ldg(val + e);

    float4 hv = *reinterpret_cast<const float4*>(h + (size_t)c * D + j * 4);
    float4 m;
    m.x = v * hv.x; m.y = v * hv.y; m.z = v * hv.z; m.w = v * hv.w;

    float* p = y + (size_t)r * D + j * 4;
    asm volatile("red.global.add.v4.f32 [%0], {%1, %2, %3, %4};"
                 :: "l"(p), "f"(m.x), "f"(m.y), "f"(m.z), "f"(m.w)
                 : "memory");
}

// ---------------------------------------------------------------------------
// out += src ; tozero = 0          (float4-vectorized)
// ---------------------------------------------------------------------------
__global__ void k_add_zero(float4* __restrict__ out,
                           const float4* __restrict__ src,
                           float4* __restrict__ tozero) {
    int i = blockIdx.x * blockDim.x + threadIdx.x;
    if (i >= ND4) return;
    float4 a = out[i], b = src[i];
    a.x += b.x; a.y += b.y; a.z += b.z; a.w += b.w;
    out[i] = a;
    tozero[i] = make_float4(0.f, 0.f, 0.f, 0.f);
}

// ---------------------------------------------------------------------------
// out = (out + src) * 0.25
// ---------------------------------------------------------------------------
__global__ void k_final(float4* __restrict__ out,
                        const float4* __restrict__ src) {
    int i = blockIdx.x * blockDim.x + threadIdx.x;
    if (i >= ND4) return;
    float4 a = out[i], b = src[i];
    a.x = (a.x + b.x) * 0.25f;
    a.y = (a.y + b.y) * 0.25f;
    a.z = (a.z + b.z) * 0.25f;
    a.w = (a.w + b.w) * 0.25f;
    out[i] = a;
}

// ---------------------------------------------------------------------------
// Inputs (metadata order): edge_row[int32 E], edge_col[int32 E],
//                          edge_val[f32 E],  x[f32 N*D]
// Output: f32 N*D
// ---------------------------------------------------------------------------
extern "C" void kernel_launch(void* const* d_in, const int* in_sizes, int n_in,
                              void* d_out, int out_size) {
    const int*   edge_row = (const int*)  d_in[0];
    const int*   edge_col = (const int*)  d_in[1];
    const float* edge_val = (const float*)d_in[2];
    const float* x        = (const float*)d_in[3];
    float*       out      = (float*)      d_out;

    const int nE = in_sizes[0];

    float* buf0;
    float* buf1;
    cudaGetSymbolAddress((void**)&buf0, g_buf0);
    cudaGetSymbolAddress((void**)&buf1, g_buf1);

    const int TB = 256;
    const int gridV = (ND4 + TB - 1) / TB;                 // elementwise grids
    const int gridE = (nE * 8 + TB - 1) / TB;              // spmm grid

    // out = x ; buf0 = buf1 = 0
    k_init<<<gridV, TB>>>((const float4*)x, (float4*)out);

    // layer 1: buf0 = P x ; out += buf0 (buf1 stays zero)
    k_spmm<<<gridE, TB>>>(edge_row, edge_col, edge_val, x, buf0, nE);
    k_add_zero<<<gridV, TB>>>((float4*)out, (const float4*)buf0, (float4*)buf1);

    // wait — k_add_zero above zeroes buf1, which is the NEXT spmm target. Good.

    // layer 2: buf1 = P buf0 ; out += buf1 ; zero buf0 for layer 3
    k_spmm<<<gridE, TB>>>(edge_row, edge_col, edge_val, buf0, buf1, nE);
    k_add_zero<<<gridV, TB>>>((float4*)out, (const float4*)buf1, (float4*)buf0);

    // layer 3: buf0 = P buf1 ; out = (out + buf0) / 4
    k_spmm<<<gridE, TB>>>(edge_row, edge_col, edge_val, buf1, buf0, nE);
    k_final<<<gridV, TB>>>((float4*)out, (const float4*)buf0);
}

// round 4
// speedup vs baseline: 1.1848x; 1.1848x over previous
#include <cuda_runtime.h>
#include <cuda_bf16.h>
#include <cstdint>

// LightGCN: out = (x + Px + P^2x + P^3x) / 4, P = COO SpMM (E=1.6M, N=100k, D=32).
// R3: latency-bound fix — 4-edge unroll per 8-lane group (4x MLP), vectorized
// edge-meta loads (int4/float4 broadcast), fused epilogue (3 layer buffers +
// single final combine).

static constexpr int N_NODES = 100000;
static constexpr int D       = 32;
static constexpr int ND      = N_NODES * D;   // 3,200,000 floats
static constexpr int ND4     = ND / 4;

// Scratch (no allocations allowed): three layer output buffers.
__device__ float g_b0[ND];
__device__ float g_b1[ND];
__device__ float g_b2[ND];

// ---------------------------------------------------------------------------
// init: zero all three layer buffers (float4-vectorized)
// ---------------------------------------------------------------------------
__global__ void k_init() {
    int i = blockIdx.x * blockDim.x + threadIdx.x;
    if (i >= ND4) return;
    float4 z = make_float4(0.f, 0.f, 0.f, 0.f);
    reinterpret_cast<float4*>(g_b0)[i] = z;
    reinterpret_cast<float4*>(g_b1)[i] = z;
    reinterpret_cast<float4*>(g_b2)[i] = z;
}

// ---------------------------------------------------------------------------
// SpMM scatter: y[row[e]] += val[e] * h[col[e]]
//
// Layout: each 8-lane group owns 4 consecutive edges [4g, 4g+4).
//   - edge meta loaded once per group as int4/int4/float4 (broadcast across
//     the 8 lanes; coalesced across the 4 groups of a warp)
//   - phase-batched: 4 gathers issued back-to-back (4x MLP), then 4 REDs
//   - lane j handles float4 chunk j of the 128B feature row
// ---------------------------------------------------------------------------
__global__ void __launch_bounds__(256) k_spmm(
        const int*   __restrict__ row,
        const int*   __restrict__ col,
        const float* __restrict__ val,
        const float* __restrict__ h,
        float*       __restrict__ y,
        int nE) {
    const int t = blockIdx.x * blockDim.x + threadIdx.x;
    const int g = t >> 3;          // group id: owns edges [4g, 4g+4)
    const int j = t & 7;           // feature chunk (16B) within the 128B row
    const int G = (nE + 3) >> 2;   // number of groups
    if (g >= G) return;

    const int e0 = g << 2;

    // Edge meta: one vector load per array, broadcast within the group.
    int4   c4 = __ldg(reinterpret_cast<const int4*>(col) + g);
    int4   r4 = __ldg(reinterpret_cast<const int4*>(row) + g);
    float4 v4 = __ldg(reinterpret_cast<const float4*>(val) + g);

    const int   c[4] = {c4.x, c4.y, c4.z, c4.w};
    const int   r[4] = {r4.x, r4.y, r4.z, r4.w};
    const float v[4] = {v4.x, v4.y, v4.z, v4.w};

    // Phase 1: issue all 4 gathers (independent -> 4x MLP).
    float4 hv[4];
#pragma unroll
    for (int k = 0; k < 4; k++) {
        int cc = (e0 + k < nE) ? c[k] : 0;
        hv[k] = *reinterpret_cast<const float4*>(h + (size_t)cc * D + j * 4);
    }

    // Phase 2: scale + vector reduction (fire-and-forget, no scoreboard wait).
#pragma unroll
    for (int k = 0; k < 4; k++) {
        if (e0 + k >= nE) break;
        float4 m;
        m.x = v[k] * hv[k].x;
        m.y = v[k] * hv[k].y;
        m.z = v[k] * hv[k].z;
        m.w = v[k] * hv[k].w;
        float* p = y + (size_t)r[k] * D + j * 4;
        asm volatile("red.global.add.v4.f32 [%0], {%1, %2, %3, %4};"
                     :: "l"(p), "f"(m.x), "f"(m.y), "f"(m.z), "f"(m.w)
                     : "memory");
    }
}

// ---------------------------------------------------------------------------
// final: out = 0.25 * (x + b0 + b1 + b2)
// ---------------------------------------------------------------------------
__global__ void k_final(const float4* __restrict__ x,
                        float4*       __restrict__ out) {
    int i = blockIdx.x * blockDim.x + threadIdx.x;
    if (i >= ND4) return;
    float4 a  = x[i];
    float4 b0 = reinterpret_cast<const float4*>(g_b0)[i];
    float4 b1 = reinterpret_cast<const float4*>(g_b1)[i];
    float4 b2 = reinterpret_cast<const float4*>(g_b2)[i];
    float4 o;
    o.x = (a.x + b0.x + b1.x + b2.x) * 0.25f;
    o.y = (a.y + b0.y + b1.y + b2.y) * 0.25f;
    o.z = (a.z + b0.z + b1.z + b2.z) * 0.25f;
    o.w = (a.w + b0.w + b1.w + b2.w) * 0.25f;
    out[i] = o;
}

// ---------------------------------------------------------------------------
// Inputs (metadata order): edge_row[int32 E], edge_col[int32 E],
//                          edge_val[f32 E],  x[f32 N*D]
// Output: f32 N*D
// ---------------------------------------------------------------------------
extern "C" void kernel_launch(void* const* d_in, const int* in_sizes, int n_in,
                              void* d_out, int out_size) {
    const int*   edge_row = (const int*)  d_in[0];
    const int*   edge_col = (const int*)  d_in[1];
    const float* edge_val = (const float*)d_in[2];
    const float* x        = (const float*)d_in[3];
    float*       out      = (float*)      d_out;

    const int nE = in_sizes[0];

    float *b0, *b1, *b2;
    cudaGetSymbolAddress((void**)&b0, g_b0);
    cudaGetSymbolAddress((void**)&b1, g_b1);
    cudaGetSymbolAddress((void**)&b2, g_b2);

    const int TB = 256;
    const int gridV = (ND4 + TB - 1) / TB;

    const int G       = (nE + 3) / 4;          // edge groups
    const int threads = G * 8;                 // 8 lanes per group
    const int gridE   = (threads + TB - 1) / TB;

    // zero the three layer buffers
    k_init<<<gridV, TB>>>();

    // b0 = P x ; b1 = P b0 ; b2 = P b1
    k_spmm<<<gridE, TB>>>(edge_row, edge_col, edge_val, x,  b0, nE);
    k_spmm<<<gridE, TB>>>(edge_row, edge_col, edge_val, b0, b1, nE);
    k_spmm<<<gridE, TB>>>(edge_row, edge_col, edge_val, b1, b2, nE);

    // out = (x + b0 + b1 + b2) / 4
    k_final<<<gridV, TB>>>((const float4*)x, (float4*)out);
}

// round 6
// speedup vs baseline: 1.2077x; 1.0193x over previous
#include <cuda_runtime.h>
#include <cuda_bf16.h>
#include <cstdint>

// LightGCN: out = (x + Px + P^2x + P^3x) / 4, P = COO SpMM (E=1.6M, N=100k, D=32).
// R4: L1-wavefront reduction — warp-cooperative edge-meta loads (3 coalesced
// 128B loads per 32 edges instead of 24 broadcast loads), distributed to the
// 8-lane edge groups via shuffles. Gather/RED structure unchanged (MLP=4).

static constexpr int N_NODES = 100000;
static constexpr int D       = 32;
static constexpr int ND      = N_NODES * D;   // 3,200,000 floats
static constexpr int ND4     = ND / 4;

// Scratch (no allocations allowed): three layer output buffers.
__device__ float g_b0[ND];
__device__ float g_b1[ND];
__device__ float g_b2[ND];

// ---------------------------------------------------------------------------
// init: zero all three layer buffers (float4-vectorized)
// ---------------------------------------------------------------------------
__global__ void k_init() {
    int i = blockIdx.x * blockDim.x + threadIdx.x;
    if (i >= ND4) return;
    float4 z = make_float4(0.f, 0.f, 0.f, 0.f);
    reinterpret_cast<float4*>(g_b0)[i] = z;
    reinterpret_cast<float4*>(g_b1)[i] = z;
    reinterpret_cast<float4*>(g_b2)[i] = z;
}

// ---------------------------------------------------------------------------
// SpMM scatter: y[row[e]] += val[e] * h[col[e]]
//
// Each warp owns 32 consecutive edges:
//   - lanes 0..31 cooperatively load meta (col/row/val) with 3 coalesced
//     128B loads (3 L1 wavefronts per 32 edges, was 24)
//   - warp = 4 groups of 8 lanes; group g processes edges in two pipelined
//     batches of 4 (gathers batched for MLP=4, then fire-and-forget REDs)
//   - lane j within a group handles float4 chunk j of the 128B feature row
// ---------------------------------------------------------------------------
__global__ void __launch_bounds__(256) k_spmm(
        const int*   __restrict__ row,
        const int*   __restrict__ col,
        const float* __restrict__ val,
        const float* __restrict__ h,
        float*       __restrict__ y,
        int nE) {
    const int t    = blockIdx.x * blockDim.x + threadIdx.x;
    const int warp = t >> 5;
    const int lane = t & 31;
    const int g    = lane >> 3;   // edge group within warp (0..3)
    const int j    = lane & 7;    // 16B feature chunk within the 128B row

    const int eb = warp * 32;     // first edge owned by this warp
    if (eb >= nE) return;

    // Cooperative meta load: lane l holds meta of edge eb+l.
    int c_l = 0, r_l = 0;
    float v_l = 0.f;
    const int el = eb + lane;
    if (el < nE) {
        c_l = __ldg(col + el);
        r_l = __ldg(row + el);
        v_l = __ldg(val + el);
    }

    const float* hj = h + j * 4;
    float*       yj = y + j * 4;

#pragma unroll
    for (int it = 0; it < 2; it++) {
        const int base = it * 16 + g * 4;   // source-lane base for this batch
        const int e0   = eb + base;

        int   c[4], r[4];
        float v[4];
#pragma unroll
        for (int k = 0; k < 4; k++) {
            c[k] = __shfl_sync(0xffffffffu, c_l, base + k);
            r[k] = __shfl_sync(0xffffffffu, r_l, base + k);
            v[k] = __shfl_sync(0xffffffffu, v_l, base + k);
        }

        // Phase 1: issue 4 independent gathers (MLP=4).
        float4 hv[4];
#pragma unroll
        for (int k = 0; k < 4; k++) {
            const int cc = (e0 + k < nE) ? c[k] : 0;
            hv[k] = *reinterpret_cast<const float4*>(hj + (size_t)cc * D);
        }

        // Phase 2: scale + vector reduction (no scoreboard wait on RED).
#pragma unroll
        for (int k = 0; k < 4; k++) {
            if (e0 + k >= nE) break;
            float4 m;
            m.x = v[k] * hv[k].x;
            m.y = v[k] * hv[k].y;
            m.z = v[k] * hv[k].z;
            m.w = v[k] * hv[k].w;
            float* p = yj + (size_t)r[k] * D;
            asm volatile("red.global.add.v4.f32 [%0], {%1, %2, %3, %4};"
                         :: "l"(p), "f"(m.x), "f"(m.y), "f"(m.z), "f"(m.w)
                         : "memory");
        }
    }
}

// ---------------------------------------------------------------------------
// final: out = 0.25 * (x + b0 + b1 + b2)
// ---------------------------------------------------------------------------
__global__ void k_final(const float4* __restrict__ x,
                        float4*       __restrict__ out) {
    int i = blockIdx.x * blockDim.x + threadIdx.x;
    if (i >= ND4) return;
    float4 a  = x[i];
    float4 b0 = reinterpret_cast<const float4*>(g_b0)[i];
    float4 b1 = reinterpret_cast<const float4*>(g_b1)[i];
    float4 b2 = reinterpret_cast<const float4*>(g_b2)[i];
    float4 o;
    o.x = (a.x + b0.x + b1.x + b2.x) * 0.25f;
    o.y = (a.y + b0.y + b1.y + b2.y) * 0.25f;
    o.z = (a.z + b0.z + b1.z + b2.z) * 0.25f;
    o.w = (a.w + b0.w + b1.w + b2.w) * 0.25f;
    out[i] = o;
}

// ---------------------------------------------------------------------------
// Inputs (metadata order): edge_row[int32 E], edge_col[int32 E],
//                          edge_val[f32 E],  x[f32 N*D]
// Output: f32 N*D
// ---------------------------------------------------------------------------
extern "C" void kernel_launch(void* const* d_in, const int* in_sizes, int n_in,
                              void* d_out, int out_size) {
    const int*   edge_row = (const int*)  d_in[0];
    const int*   edge_col = (const int*)  d_in[1];
    const float* edge_val = (const float*)d_in[2];
    const float* x        = (const float*)d_in[3];
    float*       out      = (float*)      d_out;

    const int nE = in_sizes[0];

    float *b0, *b1, *b2;
    cudaGetSymbolAddress((void**)&b0, g_b0);
    cudaGetSymbolAddress((void**)&b1, g_b1);
    cudaGetSymbolAddress((void**)&b2, g_b2);

    const int TB = 256;
    const int gridV = (ND4 + TB - 1) / TB;

    const int nWarps  = (nE + 31) / 32;        // one warp per 32 edges
    const int threads = nWarps * 32;
    const int gridE   = (threads + TB - 1) / TB;

    // zero the three layer buffers
    k_init<<<gridV, TB>>>();

    // b0 = P x ; b1 = P b0 ; b2 = P b1
    k_spmm<<<gridE, TB>>>(edge_row, edge_col, edge_val, x,  b0, nE);
    k_spmm<<<gridE, TB>>>(edge_row, edge_col, edge_val, b0, b1, nE);
    k_spmm<<<gridE, TB>>>(edge_row, edge_col, edge_val, b1, b2, nE);

    // out = (x + b0 + b1 + b2) / 4
    k_final<<<gridV, TB>>>((const float4*)x, (float4*)out);
}

// round 8
// speedup vs baseline: 1.3055x; 1.0809x over previous
#include <cuda_runtime.h>
#include <cuda_bf16.h>
#include <cstdint>

// LightGCN: out = (x + Px + P^2x + P^3x)/4, P = COO SpMM (E=1.6M, N=100k, D=32).
// R6: atomic-free CSR-gather SpMM. Per call: counting-sort edges by row
// (hist -> 2-level scan -> scatter packed (col,val)), then 3 gather SpMM
// layers, each fusing the "out += layer" accumulation (last layer scales 0.25).

static constexpr int N_NODES     = 100000;
static constexpr int N_EDGES_MAX = 1600000;
static constexpr int D   = 32;
static constexpr int ND  = N_NODES * D;       // 3,200,000 floats
static constexpr int ND4 = ND / 4;

static constexpr int SCAN_T  = 512;
static constexpr int SCAN_NB = (N_NODES + SCAN_T - 1) / SCAN_T;   // 196

// Scratch (no allocations): CSR build state + two layer ping-pong buffers.
__device__ float g_b0[ND];
__device__ float g_b1[ND];
__device__ int   g_cnt[N_NODES];     // degree per row
__device__ int   g_off[N_NODES];     // exclusive row offsets
__device__ int   g_fill[N_NODES];    // scatter cursors
__device__ int2  g_emeta[N_EDGES_MAX]; // packed (col, val-as-int) sorted by row
__device__ int   g_bsum[256];        // per-scan-block sums (SCAN_NB <= 256)

// ---------------------------------------------------------------------------
__global__ void k_zero_cnt() {
    int i = blockIdx.x * blockDim.x + threadIdx.x;
    if (i < N_NODES) g_cnt[i] = 0;
}

__global__ void k_hist(const int* __restrict__ row, int nE) {
    int e = blockIdx.x * blockDim.x + threadIdx.x;
    if (e < nE) atomicAdd(&g_cnt[__ldg(row + e)], 1);
}

// Per-block inclusive scan of degrees; writes block-local exclusive offsets
// and the block total.
__global__ void k_scan_block() {
    __shared__ int s[SCAN_T];
    const int tid = threadIdx.x;
    const int i   = blockIdx.x * SCAN_T + tid;
    int v = (i < N_NODES) ? g_cnt[i] : 0;
    s[tid] = v;
    __syncthreads();
#pragma unroll
    for (int d = 1; d < SCAN_T; d <<= 1) {
        int t = (tid >= d) ? s[tid - d] : 0;
        __syncthreads();
        s[tid] += t;
        __syncthreads();
    }
    if (i < N_NODES) g_off[i] = s[tid] - v;          // exclusive, block-local
    if (tid == SCAN_T - 1) g_bsum[blockIdx.x] = s[tid];
}

// Single-block exclusive scan of the block sums (SCAN_NB <= 256).
__global__ void k_scan_bsum() {
    __shared__ int s[256];
    const int tid = threadIdx.x;
    int v = (tid < SCAN_NB) ? g_bsum[tid] : 0;
    s[tid] = v;
    __syncthreads();
#pragma unroll
    for (int d = 1; d < 256; d <<= 1) {
        int t = (tid >= d) ? s[tid - d] : 0;
        __syncthreads();
        s[tid] += t;
        __syncthreads();
    }
    if (tid < SCAN_NB) g_bsum[tid] = s[tid] - v;     // exclusive
}

__global__ void k_scan_apply() {
    int i = blockIdx.x * blockDim.x + threadIdx.x;
    if (i >= N_NODES) return;
    int o = g_off[i] + g_bsum[i / SCAN_T];
    g_off[i]  = o;
    g_fill[i] = o;
}

// Scatter edges into row-sorted order, packing (col, val) into 8 bytes.
__global__ void k_scatter(const int*   __restrict__ row,
                          const int*   __restrict__ col,
                          const float* __restrict__ val,
                          int nE) {
    int e = blockIdx.x * blockDim.x + threadIdx.x;
    if (e >= nE) return;
    int r   = __ldg(row + e);
    int pos = atomicAdd(&g_fill[r], 1);
    g_emeta[pos] = make_int2(__ldg(col + e), __float_as_int(__ldg(val + e)));
}

// out = x
__global__ void k_initout(const float4* __restrict__ x, float4* __restrict__ out) {
    int i = blockIdx.x * blockDim.x + threadIdx.x;
    if (i < ND4) out[i] = x[i];
}

// ---------------------------------------------------------------------------
// CSR gather SpMM, fused with the LightGCN accumulation:
//   acc      = sum_{e in row r} val[e] * h[col[e]]          (registers)
//   y[r]     = acc                                          (if storeY)
//   out[r]   = (out[r] + acc) * scale                       (scale: 1 or 0.25)
//
// 8-lane group per row; lane j owns float4 chunk j of the 128B row.
// Meta loaded 8 edges at a time (coalesced within the group), broadcast via
// group-masked shuffles; gathers batched 4-wide for MLP.
// ---------------------------------------------------------------------------
__global__ void __launch_bounds__(256) k_spmm_csr(
        const float* __restrict__ h,
        float*       __restrict__ y,
        float*       __restrict__ out,
        float scale, int storeY) {
    const int t    = blockIdx.x * blockDim.x + threadIdx.x;
    const int grp  = t >> 3;            // row id
    const int j    = t & 7;             // 16B chunk within the 128B row
    if (grp >= N_NODES) return;

    const int lane  = threadIdx.x & 31;
    const unsigned gmask = 0xFFu << (lane & 24);   // this 8-lane group

    const int start = __ldg(&g_off[grp]);
    const int deg   = __ldg(&g_cnt[grp]);

    const float* hj = h + j * 4;
    float4 acc = make_float4(0.f, 0.f, 0.f, 0.f);

    for (int base = 0; base < deg; base += 8) {
        // lane j of the group loads meta for edge (start+base+j): coalesced 64B
        int2 m = make_int2(0, 0);
        if (base + j < deg) m = __ldg(&g_emeta[start + base + j]);
        const int gb = lane & 24;

#pragma unroll
        for (int half = 0; half < 2; half++) {
            if (base + half * 4 >= deg) break;
            int   c[4];
            float v[4];
#pragma unroll
            for (int k = 0; k < 4; k++) {
                const int sl = gb + half * 4 + k;
                c[k] = __shfl_sync(gmask, m.x, sl);
                v[k] = __int_as_float(__shfl_sync(gmask, m.y, sl));
            }
            // batched independent gathers (MLP=4)
            float4 hv[4];
#pragma unroll
            for (int k = 0; k < 4; k++) {
                if (base + half * 4 + k < deg)
                    hv[k] = *reinterpret_cast<const float4*>(hj + (size_t)c[k] * D);
            }
#pragma unroll
            for (int k = 0; k < 4; k++) {
                if (base + half * 4 + k < deg) {
                    acc.x += v[k] * hv[k].x;
                    acc.y += v[k] * hv[k].y;
                    acc.z += v[k] * hv[k].z;
                    acc.w += v[k] * hv[k].w;
                }
            }
        }
    }

    const size_t o = (size_t)grp * D + j * 4;
    if (storeY)
        *reinterpret_cast<float4*>(y + o) = acc;

    float4 ov = *reinterpret_cast<const float4*>(out + o);
    ov.x = (ov.x + acc.x) * scale;
    ov.y = (ov.y + acc.y) * scale;
    ov.z = (ov.z + acc.z) * scale;
    ov.w = (ov.w + acc.w) * scale;
    *reinterpret_cast<float4*>(out + o) = ov;
}

// ---------------------------------------------------------------------------
// Inputs (metadata order): edge_row[int32 E], edge_col[int32 E],
//                          edge_val[f32 E],  x[f32 N*D]
// Output: f32 N*D
// ---------------------------------------------------------------------------
extern "C" void kernel_launch(void* const* d_in, const int* in_sizes, int n_in,
                              void* d_out, int out_size) {
    const int*   edge_row = (const int*)  d_in[0];
    const int*   edge_col = (const int*)  d_in[1];
    const float* edge_val = (const float*)d_in[2];
    const float* x        = (const float*)d_in[3];
    float*       out      = (float*)      d_out;

    const int nE = in_sizes[0];

    float *b0, *b1;
    cudaGetSymbolAddress((void**)&b0, g_b0);
    cudaGetSymbolAddress((void**)&b1, g_b1);

    const int TB     = 256;
    const int gridN  = (N_NODES + TB - 1) / TB;   // per-node
    const int gridE  = (nE + TB - 1) / TB;        // per-edge
    const int gridV  = (ND4 + TB - 1) / TB;       // per-float4 of features
    const int gridS  = (N_NODES * 8 + TB - 1) / TB; // spmm: 8 lanes per row

    // --- CSR build (counting sort by row) ---
    k_zero_cnt <<<gridN, TB>>>();
    k_hist     <<<gridE, TB>>>(edge_row, nE);
    k_scan_block<<<SCAN_NB, SCAN_T>>>();
    k_scan_bsum <<<1, 256>>>();
    k_scan_apply<<<gridN, TB>>>();
    k_scatter  <<<gridE, TB>>>(edge_row, edge_col, edge_val, nE);

    // --- out = x ---
    k_initout<<<gridV, TB>>>((const float4*)x, (float4*)out);

    // --- 3 propagation layers, accumulation fused ---
    k_spmm_csr<<<gridS, TB>>>(x,  b0, out, 1.0f,  1);   // b0 = Px;   out += b0
    k_spmm_csr<<<gridS, TB>>>(b0, b1, out, 1.0f,  1);   // b1 = Pb0;  out += b1
    k_spmm_csr<<<gridS, TB>>>(b1, b0, out, 0.25f, 0);   // out = (out + Pb1)/4
}

// round 9
// speedup vs baseline: 1.3962x; 1.0695x over previous
#include <cuda_runtime.h>
#include <cuda_bf16.h>
#include <cstdint>

// LightGCN: out = (x + Px + P^2x + P^3x)/4, P = COO SpMM (E=1.6M, N=100k, D=32).
// R8: serial-chain compression. CSR build is now 4 launches:
//   zero -> hist -> scan(single kernel, atomic block-base; row order need not
//   be prefix-ordered, only contiguous) -> scatter
// and the "out = x" pass is fused into layer 1 (out = x + Px).
// SpMM layers are at their L2-gather roofline and unchanged.

static constexpr int N_NODES     = 100000;
static constexpr int N_EDGES_MAX = 1600000;
static constexpr int D   = 32;
static constexpr int ND  = N_NODES * D;       // 3,200,000 floats

static constexpr int SCAN_T  = 512;
static constexpr int SCAN_NB = (N_NODES + SCAN_T - 1) / SCAN_T;   // 196

// Scratch (no allocations): CSR build state + two layer ping-pong buffers.
__device__ float g_b0[ND];
__device__ float g_b1[ND];
__device__ int   g_cnt[N_NODES];       // degree per row
__device__ int   g_off[N_NODES];       // row start offsets (block-permuted CSR)
__device__ int   g_fill[N_NODES];      // scatter cursors
__device__ int2  g_emeta[N_EDGES_MAX]; // packed (col, val) grouped by row
__device__ int   g_total;              // global allocation cursor for scan

// ---------------------------------------------------------------------------
__global__ void k_zero_cnt() {
    int i = blockIdx.x * blockDim.x + threadIdx.x;
    if (i < N_NODES) g_cnt[i] = 0;
    if (i == 0) g_total = 0;
}

__global__ void k_hist(const int* __restrict__ row, int nE) {
    int e = blockIdx.x * blockDim.x + threadIdx.x;
    if (e < nE) atomicAdd(&g_cnt[__ldg(row + e)], 1);
}

// Single-kernel "scan": each block scans its 512 degrees locally, then claims
// a contiguous range of the edge array with one atomicAdd. Rows from different
// blocks end up in arbitrary relative order in g_emeta — harmless, since the
// SpMM only needs (off, cnt) per row, not global ordering.
__global__ void k_scan() {
    __shared__ int s[SCAN_T];
    __shared__ int sbase;
    const int tid = threadIdx.x;
    const int i   = blockIdx.x * SCAN_T + tid;
    int v = (i < N_NODES) ? g_cnt[i] : 0;
    s[tid] = v;
    __syncthreads();
#pragma unroll
    for (int d = 1; d < SCAN_T; d <<= 1) {
        int t = (tid >= d) ? s[tid - d] : 0;
        __syncthreads();
        s[tid] += t;
        __syncthreads();
    }
    if (tid == SCAN_T - 1) sbase = atomicAdd(&g_total, s[tid]);
    __syncthreads();
    if (i < N_NODES) {
        int o = sbase + s[tid] - v;     // block-local exclusive + block base
        g_off[i]  = o;
        g_fill[i] = o;
    }
}

// Scatter edges into row-grouped order, packing (col, val) into 8 bytes.
__global__ void k_scatter(const int*   __restrict__ row,
                          const int*   __restrict__ col,
                          const float* __restrict__ val,
                          int nE) {
    int e = blockIdx.x * blockDim.x + threadIdx.x;
    if (e >= nE) return;
    int r   = __ldg(row + e);
    int pos = atomicAdd(&g_fill[r], 1);
    g_emeta[pos] = make_int2(__ldg(col + e), __float_as_int(__ldg(val + e)));
}

// ---------------------------------------------------------------------------
// CSR gather SpMM, fused with the LightGCN accumulation:
//   acc    = sum_{e in row r} val[e] * h[col[e]]     (registers)
//   y[r]   = acc                                     (if storeY)
//   out[r] = (base[r] + acc) * scale                 (base = x or out)
//
// 8-lane group per row; lane j owns float4 chunk j of the 128B row.
// Meta loaded 8 edges at a time (coalesced), broadcast via group-masked
// shuffles; gathers batched 4-wide for MLP.
// ---------------------------------------------------------------------------
__global__ void __launch_bounds__(256) k_spmm_csr(
        const float* __restrict__ h,
        float*       __restrict__ y,
        const float* __restrict__ base,
        float*       __restrict__ out,
        float scale, int storeY) {
    const int t   = blockIdx.x * blockDim.x + threadIdx.x;
    const int grp = t >> 3;            // row id
    const int j   = t & 7;             // 16B chunk within the 128B row
    if (grp >= N_NODES) return;

    const int lane = threadIdx.x & 31;
    const unsigned gmask = 0xFFu << (lane & 24);   // this 8-lane group
    const int gb = lane & 24;

    const int start = __ldg(&g_off[grp]);
    const int deg   = __ldg(&g_cnt[grp]);

    const float* hj = h + j * 4;
    float4 acc = make_float4(0.f, 0.f, 0.f, 0.f);

    for (int b = 0; b < deg; b += 8) {
        // lane j of the group loads meta for edge (start+b+j): coalesced 64B
        int2 m = make_int2(0, 0);
        if (b + j < deg) m = __ldg(&g_emeta[start + b + j]);

#pragma unroll
        for (int half = 0; half < 2; half++) {
            if (b + half * 4 >= deg) break;
            int   c[4];
            float v[4];
#pragma unroll
            for (int k = 0; k < 4; k++) {
                const int sl = gb + half * 4 + k;
                c[k] = __shfl_sync(gmask, m.x, sl);
                v[k] = __int_as_float(__shfl_sync(gmask, m.y, sl));
            }
            float4 hv[4];                       // batched gathers (MLP=4)
#pragma unroll
            for (int k = 0; k < 4; k++) {
                if (b + half * 4 + k < deg)
                    hv[k] = *reinterpret_cast<const float4*>(hj + (size_t)c[k] * D);
            }
#pragma unroll
            for (int k = 0; k < 4; k++) {
                if (b + half * 4 + k < deg) {
                    acc.x += v[k] * hv[k].x;
                    acc.y += v[k] * hv[k].y;
                    acc.z += v[k] * hv[k].z;
                    acc.w += v[k] * hv[k].w;
                }
            }
        }
    }

    const size_t o = (size_t)grp * D + j * 4;
    if (storeY)
        *reinterpret_cast<float4*>(y + o) = acc;

    float4 bv = *reinterpret_cast<const float4*>(base + o);
    bv.x = (bv.x + acc.x) * scale;
    bv.y = (bv.y + acc.y) * scale;
    bv.z = (bv.z + acc.z) * scale;
    bv.w = (bv.w + acc.w) * scale;
    *reinterpret_cast<float4*>(out + o) = bv;
}

// ---------------------------------------------------------------------------
// Inputs (metadata order): edge_row[int32 E], edge_col[int32 E],
//                          edge_val[f32 E],  x[f32 N*D]
// Output: f32 N*D
// ---------------------------------------------------------------------------
extern "C" void kernel_launch(void* const* d_in, const int* in_sizes, int n_in,
                              void* d_out, int out_size) {
    const int*   edge_row = (const int*)  d_in[0];
    const int*   edge_col = (const int*)  d_in[1];
    const float* edge_val = (const float*)d_in[2];
    const float* x        = (const float*)d_in[3];
    float*       out      = (float*)      d_out;

    const int nE = in_sizes[0];

    float *b0, *b1;
    cudaGetSymbolAddress((void**)&b0, g_b0);
    cudaGetSymbolAddress((void**)&b1, g_b1);

    const int TB    = 256;
    const int gridN = (N_NODES + TB - 1) / TB;        // per-node
    const int gridE = (nE + TB - 1) / TB;             // per-edge
    const int gridS = (N_NODES * 8 + TB - 1) / TB;    // spmm: 8 lanes per row

    // --- CSR build: 4 launches ---
    k_zero_cnt<<<gridN, TB>>>();
    k_hist    <<<gridE, TB>>>(edge_row, nE);
    k_scan    <<<SCAN_NB, SCAN_T>>>();
    k_scatter <<<gridE, TB>>>(edge_row, edge_col, edge_val, nE);

    // --- 3 propagation layers, accumulation fused (out=x pass fused into L1) ---
    k_spmm_csr<<<gridS, TB>>>(x,  b0, x,   out, 1.0f,  1);  // b0=Px;  out = x + b0
    k_spmm_csr<<<gridS, TB>>>(b0, b1, out, out, 1.0f,  1);  // b1=Pb0; out += b1
    k_spmm_csr<<<gridS, TB>>>(b1, b0, out, out, 0.25f, 0);  // out = (out + Pb1)/4
}